// round 5
// baseline (speedup 1.0000x reference)
#include <cuda_runtime.h>

#define H     128
#define N_MAX 50000
#define E_MAX 800000

// ---------------- device scratch (no allocs allowed) ----------------
__device__ int   g_cnt[N_MAX];
__device__ int   g_row[N_MAX + 1];
__device__ int   g_cur[N_MAX];
__device__ int   g_csr_src[E_MAX];
__device__ float g_csr_a[E_MAX];
__device__ float g_s[N_MAX];
__device__ float g_ga[N_MAX];
__device__ float g_gb[N_MAX];
__device__ __align__(16) float g_t2[(size_t)N_MAX * H];   // h1 + agg2 (GEMM input)
__device__ __align__(16) float g_h2[(size_t)N_MAX * H];   // layer-2 output
__device__ __align__(16) float g_u2[H];
__device__ __align__(16) float g_q2[H];
__device__ __align__(16) float g_u3[H];
__device__ __align__(16) float g_v3[H];
__device__ __align__(16) float g_ra[H];
__device__ __align__(16) float g_rb[H];
__device__ float g_consts[4];               // alpha, beta, Cout

// ---------------- precompute collapsed weight vectors ----------------
__global__ void precompute_kernel(
    const float* __restrict__ em_w, const float* __restrict__ em_b,
    const float* __restrict__ l1_w, const float* __restrict__ l1_b,
    const float* __restrict__ n1_b,
    const float* __restrict__ l2_w, const float* __restrict__ l2_b,
    const float* __restrict__ l3_w, const float* __restrict__ l3_b,
    const float* __restrict__ n3_w, const float* __restrict__ n3_b,
    const float* __restrict__ dec_w, const float* __restrict__ dec_b)
{
    int k = threadIdx.x;   // 0..127
    float u2 = 0.f, v2 = 0.f, u3 = 0.f, v3 = 0.f;
    for (int j = 0; j < H; j++) {
        float w = em_w[j], b = em_b[j];
        float w2 = l2_w[j * H + k];
        float w3 = l3_w[j * H + k];
        u2 = fmaf(w, w2, u2);  v2 = fmaf(b, w2, v2);
        u3 = fmaf(w, w3, u3);  v3 = fmaf(b, w3, v3);
    }
    g_u2[k] = u2;
    g_q2[k] = n1_b[k] + v2 + l2_b[k];   // n1_b folded into edge const
    g_u3[k] = u3;
    g_v3[k] = v3 + l3_b[k];

    float ra = 0.f, rb = 0.f;
    for (int j = 0; j < H; j++) {
        float w3 = n3_w[k * H + j];
        ra = fmaf(w3, dec_w[j], ra);
        rb = fmaf(w3, dec_w[H + j], rb);
    }
    g_ra[k] = ra;
    g_rb[k] = rb;

    if (k == 0) {
        float al = 0.f, be = 0.f, cc = dec_b[0];
        for (int j = 0; j < H; j++) {
            al = fmaf(em_w[j], l1_w[j], al);
            be = fmaf(em_b[j], l1_w[j], be);
            cc = fmaf(n3_b[j], dec_w[j] + dec_w[H + j], cc);
        }
        g_consts[0] = al;
        g_consts[1] = be + l1_b[0];
        g_consts[2] = cc;
    }
}

// ---------------- CSR build ----------------
__global__ void zero_kernel(int n)
{
    int i = blockIdx.x * blockDim.x + threadIdx.x;
    if (i < n) g_cnt[i] = 0;
}

__global__ void hist_kernel(const int* __restrict__ ei, int nE)
{
    int e = blockIdx.x * blockDim.x + threadIdx.x;
    if (e < nE) {
        int d = ei[nE + e];
        if (d >= 0 && d < N_MAX) atomicAdd(&g_cnt[d], 1);
    }
}

__global__ void scan_kernel(int n)
{
    __shared__ int ssum[1024];
    int t = threadIdx.x;
    int chunk = (n + 1023) / 1024;
    int beg = t * chunk;
    int end = min(beg + chunk, n);
    int s = 0;
    for (int i = beg; i < end; i++) s += g_cnt[i];
    ssum[t] = s;
    __syncthreads();
    for (int off = 1; off < 1024; off <<= 1) {
        int v = 0;
        if (t >= off) v = ssum[t - off];
        __syncthreads();
        ssum[t] += v;
        __syncthreads();
    }
    int run = (t == 0) ? 0 : ssum[t - 1];
    for (int i = beg; i < end; i++) {
        int c = g_cnt[i];
        g_row[i] = run;
        g_cur[i] = run;
        run += c;
    }
    if (t == 1023) g_row[n] = ssum[1023];
}

__global__ void scatter_kernel(const int* __restrict__ ei,
                               const float* __restrict__ edge_attr, int nE)
{
    int e = blockIdx.x * blockDim.x + threadIdx.x;
    if (e < nE) {
        int s = ei[e];
        int d = ei[nE + e];
        if (d >= 0 && d < N_MAX) {
            int pos = atomicAdd(&g_cur[d], 1);
            g_csr_src[pos] = s;
            g_csr_a[pos]   = edge_attr[e];
        }
    }
}

// ---------------- layer 1 (scalar): s[i] = x_i + sum relu(x_src + a*alpha + beta) ----
__global__ void layer1_kernel(const float* __restrict__ x, int n)
{
    int warp = (blockIdx.x * blockDim.x + threadIdx.x) >> 5;
    int lane = threadIdx.x & 31;
    if (warp >= n) return;
    float alpha = g_consts[0], beta = g_consts[1];
    int beg = g_row[warp], end = g_row[warp + 1];
    float acc = 0.f;
    for (int e = beg + lane; e < end; e += 32)
        acc += fmaxf(x[g_csr_src[e]] + fmaf(alpha, g_csr_a[e], beta), 0.f);
    #pragma unroll
    for (int off = 16; off > 0; off >>= 1)
        acc += __shfl_xor_sync(0xffffffffu, acc, off);
    if (lane == 0) g_s[warp] = x[warp] + acc;
}

// ---------------- layer 2 aggregate: t2 = h1 + agg2 (warp/node, 4 cols/lane) ----
__global__ void layer2_kernel(const float* __restrict__ n1_w,
                              const float* __restrict__ n1_b, int n)
{
    int warp = (blockIdx.x * blockDim.x + threadIdx.x) >> 5;
    int lane = threadIdx.x & 31;
    if (warp >= n) return;
    int c = lane * 4;
    float4 p  = *(const float4*)&n1_w[c];
    float4 nb = *(const float4*)&n1_b[c];
    float4 u2 = *(const float4*)&g_u2[c];
    float4 q2 = *(const float4*)&g_q2[c];
    float si = g_s[warp];
    float a0 = fmaf(si, p.x, nb.x);
    float a1 = fmaf(si, p.y, nb.y);
    float a2 = fmaf(si, p.z, nb.z);
    float a3 = fmaf(si, p.w, nb.w);
    int beg = g_row[warp], end = g_row[warp + 1];
    #pragma unroll 4
    for (int e = beg; e < end; e++) {
        float c1 = g_s[g_csr_src[e]];
        float c2 = g_csr_a[e];
        a0 += fmaxf(fmaf(c1, p.x, fmaf(c2, u2.x, q2.x)), 0.f);
        a1 += fmaxf(fmaf(c1, p.y, fmaf(c2, u2.y, q2.y)), 0.f);
        a2 += fmaxf(fmaf(c1, p.z, fmaf(c2, u2.z, q2.z)), 0.f);
        a3 += fmaxf(fmaf(c1, p.w, fmaf(c2, u2.w, q2.w)), 0.f);
    }
    *(float4*)&g_t2[(size_t)warp * H + c] = make_float4(a0, a1, a2, a3);
}

// ---------------- GEMM: h2 = t2 @ n2_w + n2_b  (N x 128 x 128, fp32) ----------------
#define BM 64
#define BK 32
__global__ void gemm_kernel(const float* __restrict__ n2_w,
                            const float* __restrict__ n2_b, int n)
{
    __shared__ float As[BK][BM + 4];   // transposed A tile (row = 272B, 16B multiple)
    __shared__ float Bs[BK][H];
    int block_row = blockIdx.x * BM;
    int tid = threadIdx.x;             // 256
    int tx = tid & 31;                 // col group (4 cols)
    int ty = tid >> 5;                 // row group (8 rows)
    float acc[8][4];
    #pragma unroll
    for (int m = 0; m < 8; m++)
        #pragma unroll
        for (int cc = 0; cc < 4; cc++) acc[m][cc] = 0.f;

    for (int k0 = 0; k0 < H; k0 += BK) {
        #pragma unroll
        for (int i = tid; i < BM * BK; i += 256) {
            int m = i >> 5, k = i & 31;
            int r = block_row + m;
            As[k][m] = (r < n) ? g_t2[(size_t)r * H + k0 + k] : 0.f;
        }
        #pragma unroll
        for (int i = tid; i < BK * H; i += 256) {
            int k = i >> 7, cc = i & 127;
            Bs[k][cc] = n2_w[(k0 + k) * H + cc];
        }
        __syncthreads();
        #pragma unroll
        for (int k = 0; k < BK; k++) {
            float4 al = *(float4*)&As[k][ty * 8];
            float4 ah = *(float4*)&As[k][ty * 8 + 4];
            float4 b  = *(float4*)&Bs[k][tx * 4];
            float am[8] = {al.x, al.y, al.z, al.w, ah.x, ah.y, ah.z, ah.w};
            #pragma unroll
            for (int m = 0; m < 8; m++) {
                acc[m][0] = fmaf(am[m], b.x, acc[m][0]);
                acc[m][1] = fmaf(am[m], b.y, acc[m][1]);
                acc[m][2] = fmaf(am[m], b.z, acc[m][2]);
                acc[m][3] = fmaf(am[m], b.w, acc[m][3]);
            }
        }
        __syncthreads();
    }
    float4 bias = *(const float4*)&n2_b[tx * 4];
    #pragma unroll
    for (int m = 0; m < 8; m++) {
        int r = block_row + ty * 8 + m;
        if (r < n) {
            float4 o = make_float4(acc[m][0] + bias.x, acc[m][1] + bias.y,
                                   acc[m][2] + bias.z, acc[m][3] + bias.w);
            *(float4*)&g_h2[(size_t)r * H + tx * 4] = o;
        }
    }
}

// ---------------- layer 3 aggregate + collapsed decode dot products --------------
__global__ void layer3_kernel(int n)
{
    int warp = (blockIdx.x * blockDim.x + threadIdx.x) >> 5;
    int lane = threadIdx.x & 31;
    if (warp >= n) return;
    int c = lane * 4;
    float4 u3 = *(const float4*)&g_u3[c];
    float4 v3 = *(const float4*)&g_v3[c];
    float4 acc = *(const float4*)&g_h2[(size_t)warp * H + c];   // t3 init = h2[i]
    int beg = g_row[warp], end = g_row[warp + 1];
    #pragma unroll 2
    for (int e = beg; e < end; e++) {
        int s  = g_csr_src[e];
        float a = g_csr_a[e];
        float4 hv = *(const float4*)&g_h2[(size_t)s * H + c];
        acc.x += fmaxf(hv.x + fmaf(a, u3.x, v3.x), 0.f);
        acc.y += fmaxf(hv.y + fmaf(a, u3.y, v3.y), 0.f);
        acc.z += fmaxf(hv.z + fmaf(a, u3.z, v3.z), 0.f);
        acc.w += fmaxf(hv.w + fmaf(a, u3.w, v3.w), 0.f);
    }
    float4 ra = *(const float4*)&g_ra[c];
    float4 rb = *(const float4*)&g_rb[c];
    float ga = acc.x * ra.x + acc.y * ra.y + acc.z * ra.z + acc.w * ra.w;
    float gb = acc.x * rb.x + acc.y * rb.y + acc.z * rb.z + acc.w * rb.w;
    #pragma unroll
    for (int off = 16; off > 0; off >>= 1) {
        ga += __shfl_xor_sync(0xffffffffu, ga, off);
        gb += __shfl_xor_sync(0xffffffffu, gb, off);
    }
    if (lane == 0) {
        g_ga[warp] = ga;
        g_gb[warp] = gb;
    }
}

// ---------------- decode: out[e] = ga[src] + gb[dst] + C ----------------
__global__ void out_kernel(const int* __restrict__ ei,
                           float* __restrict__ out, int nE)
{
    int e = blockIdx.x * blockDim.x + threadIdx.x;
    if (e < nE) {
        int s = ei[e];
        int d = ei[nE + e];
        out[e] = g_ga[s] + g_gb[d] + g_consts[2];
    }
}

// ---------------- launch ----------------
extern "C" void kernel_launch(void* const* d_in, const int* in_sizes, int n_in,
                              void* d_out, int out_size)
{
    const float* x         = (const float*)d_in[0];
    const int*   ei        = (const int*)d_in[1];     // int32! (JAX x64 disabled)
    const float* edge_attr = (const float*)d_in[2];
    const float* em_w      = (const float*)d_in[3];
    const float* em_b      = (const float*)d_in[4];
    const float* l1_w      = (const float*)d_in[5];
    const float* l1_b      = (const float*)d_in[6];
    const float* n1_w      = (const float*)d_in[7];
    const float* n1_b      = (const float*)d_in[8];
    const float* l2_w      = (const float*)d_in[9];
    const float* l2_b      = (const float*)d_in[10];
    const float* n2_w      = (const float*)d_in[11];
    const float* n2_b      = (const float*)d_in[12];
    const float* l3_w      = (const float*)d_in[13];
    const float* l3_b      = (const float*)d_in[14];
    const float* n3_w      = (const float*)d_in[15];
    const float* n3_b      = (const float*)d_in[16];
    const float* dec_w     = (const float*)d_in[17];
    const float* dec_b     = (const float*)d_in[18];
    float* out = (float*)d_out;

    int N = in_sizes[0];          // 50000
    int E = in_sizes[2];          // 800000

    int eb = (E + 255) / 256;
    int nb = (N + 255) / 256;
    int wb = (N + 7) / 8;         // warp-per-node blocks (8 warps/block)

    precompute_kernel<<<1, 128>>>(em_w, em_b, l1_w, l1_b, n1_b,
                                  l2_w, l2_b, l3_w, l3_b, n3_w, n3_b,
                                  dec_w, dec_b);
    zero_kernel<<<nb, 256>>>(N);
    hist_kernel<<<eb, 256>>>(ei, E);
    scan_kernel<<<1, 1024>>>(N);
    scatter_kernel<<<eb, 256>>>(ei, edge_attr, E);
    layer1_kernel<<<wb, 256>>>(x, N);
    layer2_kernel<<<wb, 256>>>(n1_w, n1_b, N);
    gemm_kernel<<<(N + BM - 1) / BM, 256>>>(n2_w, n2_b, N);
    layer3_kernel<<<wb, 256>>>(N);
    out_kernel<<<eb, 256>>>(ei, out, E);
}

// round 7
// speedup vs baseline: 1.3441x; 1.3441x over previous
#include <cuda_runtime.h>

#define H      128
#define N_MAX  50000
#define E_MAX  800000
#define SCAN_B 512
#define NB_MAX 128          // ceil(N_MAX/SCAN_B)=98 <= 128

// ---------------- device scratch (no allocs allowed) ----------------
__device__ int   g_cnt[N_MAX];
__device__ int   g_row[N_MAX + 1];
__device__ int   g_cur[N_MAX];
__device__ int   g_bsum[NB_MAX];
__device__ int   g_boff[NB_MAX];
__device__ int   g_csr_src[E_MAX];
__device__ float g_csr_a[E_MAX];
__device__ float g_s[N_MAX];
__device__ float g_ga[N_MAX];
__device__ float g_gb[N_MAX];
__device__ __align__(16) float g_t2[(size_t)N_MAX * H];   // h1 + agg2 (GEMM input)
__device__ __align__(16) float g_h2[(size_t)N_MAX * H];   // layer-2 output
__device__ __align__(16) float g_u2[H];
__device__ __align__(16) float g_q2[H];
__device__ __align__(16) float g_u3[H];
__device__ __align__(16) float g_v3[H];
__device__ __align__(16) float g_ra[H];
__device__ __align__(16) float g_rb[H];
__device__ float g_consts[4];               // alpha, beta, Cout

// ---------------- precompute collapsed weight vectors ----------------
__global__ void precompute_kernel(
    const float* __restrict__ em_w, const float* __restrict__ em_b,
    const float* __restrict__ l1_w, const float* __restrict__ l1_b,
    const float* __restrict__ n1_b,
    const float* __restrict__ l2_w, const float* __restrict__ l2_b,
    const float* __restrict__ l3_w, const float* __restrict__ l3_b,
    const float* __restrict__ n3_w, const float* __restrict__ n3_b,
    const float* __restrict__ dec_w, const float* __restrict__ dec_b)
{
    int k = threadIdx.x;   // 0..127
    float u2 = 0.f, v2 = 0.f, u3 = 0.f, v3 = 0.f;
    for (int j = 0; j < H; j++) {
        float w = em_w[j], b = em_b[j];
        float w2 = l2_w[j * H + k];
        float w3 = l3_w[j * H + k];
        u2 = fmaf(w, w2, u2);  v2 = fmaf(b, w2, v2);
        u3 = fmaf(w, w3, u3);  v3 = fmaf(b, w3, v3);
    }
    g_u2[k] = u2;
    g_q2[k] = n1_b[k] + v2 + l2_b[k];   // n1_b folded into edge const
    g_u3[k] = u3;
    g_v3[k] = v3 + l3_b[k];

    float ra = 0.f, rb = 0.f;
    for (int j = 0; j < H; j++) {
        float w3 = n3_w[k * H + j];
        ra = fmaf(w3, dec_w[j], ra);
        rb = fmaf(w3, dec_w[H + j], rb);
    }
    g_ra[k] = ra;
    g_rb[k] = rb;

    if (k == 0) {
        float al = 0.f, be = 0.f, cc = dec_b[0];
        for (int j = 0; j < H; j++) {
            al = fmaf(em_w[j], l1_w[j], al);
            be = fmaf(em_b[j], l1_w[j], be);
            cc = fmaf(n3_b[j], dec_w[j] + dec_w[H + j], cc);
        }
        g_consts[0] = al;
        g_consts[1] = be + l1_b[0];
        g_consts[2] = cc;
    }
}

// ---------------- CSR build ----------------
__global__ void zero_kernel(int n)
{
    int i = blockIdx.x * blockDim.x + threadIdx.x;
    if (i < n) g_cnt[i] = 0;
}

__global__ void hist_kernel(const int* __restrict__ ei, int nE)
{
    int e = blockIdx.x * blockDim.x + threadIdx.x;
    if (e < nE) {
        int d = ei[nE + e];
        if (d >= 0 && d < N_MAX) atomicAdd(&g_cnt[d], 1);
    }
}

// ---- phase 1: per-block sums of g_cnt ----
__global__ void scan1_kernel(int n)
{
    int i = blockIdx.x * SCAN_B + threadIdx.x;
    int v = (i < n) ? g_cnt[i] : 0;
    int lane = threadIdx.x & 31, wid = threadIdx.x >> 5;
    #pragma unroll
    for (int off = 16; off > 0; off >>= 1)
        v += __shfl_xor_sync(0xffffffffu, v, off);
    __shared__ int ws[SCAN_B / 32];
    if (lane == 0) ws[wid] = v;
    __syncthreads();
    if (threadIdx.x < 32) {
        int s = (threadIdx.x < SCAN_B / 32) ? ws[threadIdx.x] : 0;
        #pragma unroll
        for (int off = 16; off > 0; off >>= 1)
            s += __shfl_xor_sync(0xffffffffu, s, off);
        if (threadIdx.x == 0) g_bsum[blockIdx.x] = s;
    }
}

// ---- phase 2: exclusive scan of block sums (single small block) ----
__global__ void scan2_kernel(int nb, int n)
{
    int t = threadIdx.x;            // 128 >= nb
    int lane = t & 31, wid = t >> 5;
    int v = (t < nb) ? g_bsum[t] : 0;
    int x = v;
    #pragma unroll
    for (int off = 1; off < 32; off <<= 1) {
        int y = __shfl_up_sync(0xffffffffu, x, off);
        if (lane >= off) x += y;
    }
    __shared__ int wsum[4];
    if (lane == 31) wsum[wid] = x;
    __syncthreads();
    if (t == 0) {
        int r = 0;
        #pragma unroll
        for (int k = 0; k < 4; k++) { int c = wsum[k]; wsum[k] = r; r += c; }
    }
    __syncthreads();
    x += wsum[wid];
    if (t < nb) g_boff[t] = x - v;
    if (t == 127) g_row[n] = x;     // grand total
}

// ---- phase 3: block-local scan + offsets -> g_row / g_cur ----
__global__ void scan3_kernel(int n)
{
    int i = blockIdx.x * SCAN_B + threadIdx.x;
    int c = (i < n) ? g_cnt[i] : 0;
    int lane = threadIdx.x & 31, wid = threadIdx.x >> 5;
    int x = c;
    #pragma unroll
    for (int off = 1; off < 32; off <<= 1) {
        int y = __shfl_up_sync(0xffffffffu, x, off);
        if (lane >= off) x += y;
    }
    __shared__ int ws[SCAN_B / 32];
    __shared__ int wo[SCAN_B / 32];
    if (lane == 31) ws[wid] = x;
    __syncthreads();
    if (threadIdx.x == 0) {
        int r = 0;
        #pragma unroll
        for (int k = 0; k < SCAN_B / 32; k++) { wo[k] = r; r += ws[k]; }
    }
    __syncthreads();
    if (i < n) {
        int excl = x - c + wo[wid] + g_boff[blockIdx.x];
        g_row[i] = excl;
        g_cur[i] = excl;
    }
}

__global__ void scatter_kernel(const int* __restrict__ ei,
                               const float* __restrict__ edge_attr, int nE)
{
    int e = blockIdx.x * blockDim.x + threadIdx.x;
    if (e < nE) {
        int s = ei[e];
        int d = ei[nE + e];
        if (d >= 0 && d < N_MAX) {
            int pos = atomicAdd(&g_cur[d], 1);
            g_csr_src[pos] = s;
            g_csr_a[pos]   = edge_attr[e];
        }
    }
}

// ---------------- layer 1 (scalar): s[i] = x_i + sum relu(x_src + a*alpha + beta) ----
__global__ void layer1_kernel(const float* __restrict__ x, int n)
{
    int warp = (blockIdx.x * blockDim.x + threadIdx.x) >> 5;
    int lane = threadIdx.x & 31;
    if (warp >= n) return;
    float alpha = g_consts[0], beta = g_consts[1];
    int beg = g_row[warp], end = g_row[warp + 1];
    float acc = 0.f;
    for (int e = beg + lane; e < end; e += 32)
        acc += fmaxf(x[g_csr_src[e]] + fmaf(alpha, g_csr_a[e], beta), 0.f);
    #pragma unroll
    for (int off = 16; off > 0; off >>= 1)
        acc += __shfl_xor_sync(0xffffffffu, acc, off);
    if (lane == 0) g_s[warp] = x[warp] + acc;
}

// ---------------- layer 2 aggregate: t2 = h1 + agg2 (warp/node, 4 cols/lane) ----
__global__ void layer2_kernel(const float* __restrict__ n1_w,
                              const float* __restrict__ n1_b, int n)
{
    int warp = (blockIdx.x * blockDim.x + threadIdx.x) >> 5;
    int lane = threadIdx.x & 31;
    if (warp >= n) return;
    int c = lane * 4;
    float4 p  = *(const float4*)&n1_w[c];
    float4 nb = *(const float4*)&n1_b[c];
    float4 u2 = *(const float4*)&g_u2[c];
    float4 q2 = *(const float4*)&g_q2[c];
    float si = g_s[warp];
    float a0 = fmaf(si, p.x, nb.x);
    float a1 = fmaf(si, p.y, nb.y);
    float a2 = fmaf(si, p.z, nb.z);
    float a3 = fmaf(si, p.w, nb.w);
    int beg = g_row[warp], end = g_row[warp + 1];
    #pragma unroll 4
    for (int e = beg; e < end; e++) {
        float c1 = g_s[g_csr_src[e]];
        float c2 = g_csr_a[e];
        a0 += fmaxf(fmaf(c1, p.x, fmaf(c2, u2.x, q2.x)), 0.f);
        a1 += fmaxf(fmaf(c1, p.y, fmaf(c2, u2.y, q2.y)), 0.f);
        a2 += fmaxf(fmaf(c1, p.z, fmaf(c2, u2.z, q2.z)), 0.f);
        a3 += fmaxf(fmaf(c1, p.w, fmaf(c2, u2.w, q2.w)), 0.f);
    }
    *(float4*)&g_t2[(size_t)warp * H + c] = make_float4(a0, a1, a2, a3);
}

// ---------------- GEMM: h2 = t2 @ n2_w + n2_b  (N x 128 x 128, fp32) ----------------
#define BM 64
#define BK 32
__global__ void gemm_kernel(const float* __restrict__ n2_w,
                            const float* __restrict__ n2_b, int n)
{
    __shared__ float As[BK][BM + 4];   // transposed A tile (row = 272B, 16B multiple)
    __shared__ float Bs[BK][H];
    int block_row = blockIdx.x * BM;
    int tid = threadIdx.x;             // 256
    int tx = tid & 31;                 // col group (4 cols)
    int ty = tid >> 5;                 // row group (8 rows)
    float acc[8][4];
    #pragma unroll
    for (int m = 0; m < 8; m++)
        #pragma unroll
        for (int cc = 0; cc < 4; cc++) acc[m][cc] = 0.f;

    for (int k0 = 0; k0 < H; k0 += BK) {
        #pragma unroll
        for (int i = tid; i < BM * BK; i += 256) {
            int m = i >> 5, k = i & 31;
            int r = block_row + m;
            As[k][m] = (r < n) ? g_t2[(size_t)r * H + k0 + k] : 0.f;
        }
        #pragma unroll
        for (int i = tid; i < BK * H; i += 256) {
            int k = i >> 7, cc = i & 127;
            Bs[k][cc] = n2_w[(k0 + k) * H + cc];
        }
        __syncthreads();
        #pragma unroll
        for (int k = 0; k < BK; k++) {
            float4 al = *(float4*)&As[k][ty * 8];
            float4 ah = *(float4*)&As[k][ty * 8 + 4];
            float4 b  = *(float4*)&Bs[k][tx * 4];
            float am[8] = {al.x, al.y, al.z, al.w, ah.x, ah.y, ah.z, ah.w};
            #pragma unroll
            for (int m = 0; m < 8; m++) {
                acc[m][0] = fmaf(am[m], b.x, acc[m][0]);
                acc[m][1] = fmaf(am[m], b.y, acc[m][1]);
                acc[m][2] = fmaf(am[m], b.z, acc[m][2]);
                acc[m][3] = fmaf(am[m], b.w, acc[m][3]);
            }
        }
        __syncthreads();
    }
    float4 bias = *(const float4*)&n2_b[tx * 4];
    #pragma unroll
    for (int m = 0; m < 8; m++) {
        int r = block_row + ty * 8 + m;
        if (r < n) {
            float4 o = make_float4(acc[m][0] + bias.x, acc[m][1] + bias.y,
                                   acc[m][2] + bias.z, acc[m][3] + bias.w);
            *(float4*)&g_h2[(size_t)r * H + tx * 4] = o;
        }
    }
}

// ---------------- layer 3 aggregate + collapsed decode dot products --------------
__global__ void layer3_kernel(int n)
{
    int warp = (blockIdx.x * blockDim.x + threadIdx.x) >> 5;
    int lane = threadIdx.x & 31;
    if (warp >= n) return;
    int c = lane * 4;
    float4 u3 = *(const float4*)&g_u3[c];
    float4 v3 = *(const float4*)&g_v3[c];
    float4 acc = *(const float4*)&g_h2[(size_t)warp * H + c];   // t3 init = h2[i]
    int beg = g_row[warp], end = g_row[warp + 1];
    #pragma unroll 2
    for (int e = beg; e < end; e++) {
        int s  = g_csr_src[e];
        float a = g_csr_a[e];
        float4 hv = *(const float4*)&g_h2[(size_t)s * H + c];
        acc.x += fmaxf(hv.x + fmaf(a, u3.x, v3.x), 0.f);
        acc.y += fmaxf(hv.y + fmaf(a, u3.y, v3.y), 0.f);
        acc.z += fmaxf(hv.z + fmaf(a, u3.z, v3.z), 0.f);
        acc.w += fmaxf(hv.w + fmaf(a, u3.w, v3.w), 0.f);
    }
    float4 ra = *(const float4*)&g_ra[c];
    float4 rb = *(const float4*)&g_rb[c];
    float ga = acc.x * ra.x + acc.y * ra.y + acc.z * ra.z + acc.w * ra.w;
    float gb = acc.x * rb.x + acc.y * rb.y + acc.z * rb.z + acc.w * rb.w;
    #pragma unroll
    for (int off = 16; off > 0; off >>= 1) {
        ga += __shfl_xor_sync(0xffffffffu, ga, off);
        gb += __shfl_xor_sync(0xffffffffu, gb, off);
    }
    if (lane == 0) {
        g_ga[warp] = ga;
        g_gb[warp] = gb;
    }
}

// ---------------- decode: out[e] = ga[src] + gb[dst] + C ----------------
__global__ void out_kernel(const int* __restrict__ ei,
                           float* __restrict__ out, int nE)
{
    int e = blockIdx.x * blockDim.x + threadIdx.x;
    if (e < nE) {
        int s = ei[e];
        int d = ei[nE + e];
        out[e] = g_ga[s] + g_gb[d] + g_consts[2];
    }
}

// ---------------- launch ----------------
extern "C" void kernel_launch(void* const* d_in, const int* in_sizes, int n_in,
                              void* d_out, int out_size)
{
    const float* x         = (const float*)d_in[0];
    const int*   ei        = (const int*)d_in[1];     // int32 (JAX x64 disabled)
    const float* edge_attr = (const float*)d_in[2];
    const float* em_w      = (const float*)d_in[3];
    const float* em_b      = (const float*)d_in[4];
    const float* l1_w      = (const float*)d_in[5];
    const float* l1_b      = (const float*)d_in[6];
    const float* n1_w      = (const float*)d_in[7];
    const float* n1_b      = (const float*)d_in[8];
    const float* l2_w      = (const float*)d_in[9];
    const float* l2_b      = (const float*)d_in[10];
    const float* n2_w      = (const float*)d_in[11];
    const float* n2_b      = (const float*)d_in[12];
    const float* l3_w      = (const float*)d_in[13];
    const float* l3_b      = (const float*)d_in[14];
    const float* n3_w      = (const float*)d_in[15];
    const float* n3_b      = (const float*)d_in[16];
    const float* dec_w     = (const float*)d_in[17];
    const float* dec_b     = (const float*)d_in[18];
    float* out = (float*)d_out;

    int N = in_sizes[0];          // 50000
    int E = in_sizes[2];          // 800000

    int eb = (E + 255) / 256;
    int nb = (N + 255) / 256;
    int wb = (N + 7) / 8;                     // warp-per-node blocks (8 warps/block)
    int sb = (N + SCAN_B - 1) / SCAN_B;       // scan blocks (98)

    precompute_kernel<<<1, 128>>>(em_w, em_b, l1_w, l1_b, n1_b,
                                  l2_w, l2_b, l3_w, l3_b, n3_w, n3_b,
                                  dec_w, dec_b);
    zero_kernel<<<nb, 256>>>(N);
    hist_kernel<<<eb, 256>>>(ei, E);
    scan1_kernel<<<sb, SCAN_B>>>(N);
    scan2_kernel<<<1, 128>>>(sb, N);
    scan3_kernel<<<sb, SCAN_B>>>(N);
    scatter_kernel<<<eb, 256>>>(ei, edge_attr, E);
    layer1_kernel<<<wb, 256>>>(x, N);
    layer2_kernel<<<wb, 256>>>(n1_w, n1_b, N);
    gemm_kernel<<<(N + BM - 1) / BM, 256>>>(n2_w, n2_b, N);
    layer3_kernel<<<wb, 256>>>(N);
    out_kernel<<<eb, 256>>>(ei, out, E);
}